// round 14
// baseline (speedup 1.0000x reference)
#include <cuda_runtime.h>
#include <cuda_fp16.h>
#include <cstdint>
#include <cstddef>

// Problem constants
#define BATCH 4
#define SEQ   2048
#define EMB   1024
#define HEADS 16
#define DKH   64
#define MROWS (BATCH*SEQ)      // 8192

#define SCALE_Q 0.18033688f    // 0.125 * log2(e)

typedef __half h16;

// ---------------- scratch (device globals; no allocation allowed) -----------
__device__ h16   g_qb [MROWS*EMB];   // fp16 inputs
__device__ h16   g_kb [MROWS*EMB];
__device__ h16   g_vb [MROWS*EMB];
__device__ h16   g_wq [EMB*EMB];     // fp16 weights
__device__ h16   g_wk [EMB*EMB];
__device__ h16   g_wv [EMB*EMB];
__device__ h16   g_wo [EMB*EMB];
__device__ h16   g_q  [MROWS*EMB];   // q heads [bh][s][64] (pre-scaled by SCALE_Q)
__device__ h16   g_k  [MROWS*EMB];   // k heads [bh][s'][64]  (key-compacted)
__device__ h16   g_v  [MROWS*EMB];   // v heads [bh][s'][64]  (key-compacted)
__device__ h16   g_ao [MROWS*EMB];   // attention output [b*S+s][E]
__device__ int   g_perm[MROWS];      // per-batch compaction permutation
__device__ int   g_cnt [BATCH];      // per-batch unmasked-key counts

// ---------------- helpers ----------------------------------------------------
__device__ __forceinline__ uint32_t smem_u32(const void* p) {
    uint32_t a;
    asm("{ .reg .u64 t; cvta.to.shared.u64 t, %1; cvt.u32.u64 %0, t; }" : "=r"(a) : "l"(p));
    return a;
}
__device__ __forceinline__ void cp_async16_u(uint32_t saddr, const void* gsrc) {
    asm volatile("cp.async.cg.shared.global [%0], [%1], 16;\n" :: "r"(saddr), "l"(gsrc));
}
__device__ __forceinline__ void cp_commit() { asm volatile("cp.async.commit_group;\n"); }
template <int N>
__device__ __forceinline__ void cp_wait() { asm volatile("cp.async.wait_group %0;\n" :: "n"(N)); }

__device__ __forceinline__ void mma_f16(float c[4], const uint32_t a[4], const uint32_t b[2]) {
    asm volatile(
        "mma.sync.aligned.m16n8k16.row.col.f32.f16.f16.f32 "
        "{%0,%1,%2,%3}, {%4,%5,%6,%7}, {%8,%9}, {%0,%1,%2,%3};\n"
        : "+f"(c[0]), "+f"(c[1]), "+f"(c[2]), "+f"(c[3])
        : "r"(a[0]), "r"(a[1]), "r"(a[2]), "r"(a[3]), "r"(b[0]), "r"(b[1]));
}

__device__ __forceinline__ void ldsm_x4(uint32_t& r0, uint32_t& r1, uint32_t& r2, uint32_t& r3,
                                        uint32_t addr) {
    asm volatile("ldmatrix.sync.aligned.m8n8.x4.shared.b16 {%0,%1,%2,%3}, [%4];"
                 : "=r"(r0), "=r"(r1), "=r"(r2), "=r"(r3) : "r"(addr));
}
__device__ __forceinline__ void ldsm_x4t(uint32_t& r0, uint32_t& r1, uint32_t& r2, uint32_t& r3,
                                         uint32_t addr) {
    asm volatile("ldmatrix.sync.aligned.m8n8.x4.trans.shared.b16 {%0,%1,%2,%3}, [%4];"
                 : "=r"(r0), "=r"(r1), "=r"(r2), "=r"(r3) : "r"(addr));
}

__device__ __forceinline__ uint32_t packh(float lo, float hi) {
    __half2 t = __floats2half2_rn(lo, hi);   // .x = lo (low 16 bits)
    return *reinterpret_cast<uint32_t*>(&t);
}

__device__ __forceinline__ float ex2(float x) {
    float y;
    asm("ex2.approx.ftz.f32 %0, %1;" : "=f"(y) : "f"(x));
    return y;
}

// =============================================================================
// fused fp32->fp16 conversion of 3 inputs + 4 weights.
// =============================================================================
#define CVT_NI 1048576
#define CVT_NW 131072
#define CVT_GROUPS (3*CVT_NI + 4*CVT_NW)   // 3670016
#define CVT_BLOCKS (CVT_GROUPS/256)        // 14336

__global__ void cvt_all(const float* __restrict__ Q,  const float* __restrict__ K,
                        const float* __restrict__ V,  const float* __restrict__ WQ,
                        const float* __restrict__ WK, const float* __restrict__ WV,
                        const float* __restrict__ WO,
                        h16* qb, h16* kb, h16* vb, h16* wq, h16* wk, h16* wv, h16* wo)
{
    int i = blockIdx.x * 256 + threadIdx.x;
    const float* src; h16* dst; int off;
    if      (i <     CVT_NI) { src = Q;  dst = qb; off = i; }
    else if (i < 2 * CVT_NI) { src = K;  dst = kb; off = i -     CVT_NI; }
    else if (i < 3 * CVT_NI) { src = V;  dst = vb; off = i - 2 * CVT_NI; }
    else {
        int j = i - 3 * CVT_NI;
        int w = j / CVT_NW;  off = j - w * CVT_NW;
        src = (w == 0) ? WQ : (w == 1) ? WK : (w == 2) ? WV : WO;
        dst = (w == 0) ? wq : (w == 1) ? wk : (w == 2) ? wv : wo;
    }
    const float4* p = (const float4*)src + (size_t)off * 2;
    float4 f0 = p[0], f1 = p[1];
    union { h16 h[8]; uint4 u; } r;
    r.h[0] = __float2half_rn(f0.x); r.h[1] = __float2half_rn(f0.y);
    r.h[2] = __float2half_rn(f0.z); r.h[3] = __float2half_rn(f0.w);
    r.h[4] = __float2half_rn(f1.x); r.h[5] = __float2half_rn(f1.y);
    r.h[6] = __float2half_rn(f1.z); r.h[7] = __float2half_rn(f1.w);
    ((uint4*)dst)[off] = r.u;
}

// =============================================================================
// mask scan: per batch, stable partition of keys (unmasked first).
// =============================================================================
__global__ void scan_mask(const int* __restrict__ msk, int* __restrict__ perm,
                          int* __restrict__ cnt)
{
    __shared__ int wsum[8];
    const int b = blockIdx.x, t = threadIdx.x;
    const int lane = t & 31, w = t >> 5;
    const int* m = msk + b * SEQ;

    int u[8]; int local = 0;
#pragma unroll
    for (int j = 0; j < 8; j++) { u[j] = (m[t * 8 + j] == 0) ? 1 : 0; local += u[j]; }

    int x = local;
#pragma unroll
    for (int d = 1; d < 32; d <<= 1) {
        int y = __shfl_up_sync(0xffffffffu, x, d);
        if (lane >= d) x += y;
    }
    if (lane == 31) wsum[w] = x;
    __syncthreads();
    if (w == 0) {
        int s = (lane < 8) ? wsum[lane] : 0;
#pragma unroll
        for (int d = 1; d < 8; d <<= 1) {
            int y = __shfl_up_sync(0xffffffffu, s, d);
            if (lane >= d) s += y;
        }
        if (lane < 8) wsum[lane] = s;
    }
    __syncthreads();
    const int total = wsum[7];
    int pu = ((w > 0) ? wsum[w - 1] : 0) + (x - local);
#pragma unroll
    for (int j = 0; j < 8; j++) {
        const int s_idx = t * 8 + j;
        perm[b * SEQ + s_idx] = u[j] ? pu : (total + (s_idx - pu));
        pu += u[j];
    }
    if (t == 0) cnt[b] = total;
}

// =============================================================================
// Projection GEMM core: CTA tile 128x128, BK=64, 2-stage cp.async, ldmatrix.
// =============================================================================
#define PLD     144
#define PTILEB  (128*PLD)              // 18432
#define PSTAGEB (2*PTILEB)             // 36864
#define PROJ_SMEM (2*PSTAGEB)          // 73728

__device__ __forceinline__ void proj_mainloop(
    const h16* __restrict__ A, const h16* __restrict__ W,
    uint32_t sb, int tid, int lane, int wm, int wn,
    float acc[2][8][4])
{
    auto load_stage = [&](int kt) {
        const uint32_t base = sb + (kt & 1) * PSTAGEB;
#pragma unroll
        for (int i = 0; i < 4; i++) {
            int idx = tid + i * 256;
            int r = idx >> 3, c = idx & 7;
            cp_async16_u(base + r * PLD + c * 16,          A + (size_t)r * EMB + kt * 64 + c * 8);
            cp_async16_u(base + PTILEB + r * PLD + c * 16, W + (size_t)r * EMB + kt * 64 + c * 8);
        }
        cp_commit();
    };

    const uint32_t aRowOff = (uint32_t)((wm * 32 + (lane & 15)) * PLD + (lane >> 4) * 16);
    const uint32_t bRowOff = (uint32_t)((wn * 64 + (lane >> 4) * 8 + (lane & 7)) * PLD
                                        + ((lane >> 3) & 1) * 16);

    load_stage(0); load_stage(1);
    const int NKT = EMB / 64;
    for (int kt = 0; kt < NKT; kt++) {
        if (kt == NKT - 1) cp_wait<0>(); else cp_wait<1>();
        __syncthreads();
        const uint32_t Sa = sb + (kt & 1) * PSTAGEB;
        const uint32_t Sw = Sa + PTILEB;
#pragma unroll
        for (int ks = 0; ks < 4; ks++) {
            const uint32_t kb = ks * 32;
            uint32_t a[2][4], b[8][2];
            ldsm_x4(a[0][0], a[0][1], a[0][2], a[0][3], Sa + aRowOff + kb);
            ldsm_x4(a[1][0], a[1][1], a[1][2], a[1][3], Sa + aRowOff + 16 * PLD + kb);
#pragma unroll
            for (int nt2 = 0; nt2 < 4; nt2++)
                ldsm_x4(b[2*nt2][0], b[2*nt2][1], b[2*nt2+1][0], b[2*nt2+1][1],
                        Sw + bRowOff + nt2 * 16 * PLD + kb);
#pragma unroll
            for (int mt = 0; mt < 2; mt++)
#pragma unroll
                for (int nt = 0; nt < 8; nt++)
                    mma_f16(acc[mt][nt], a[mt], b[nt]);
        }
        __syncthreads();
        if (kt + 2 < NKT) load_stage(kt + 2);
    }
}

// ---- merged Q/K/V projection: z selects input/weight; K/V rows permuted -----
__global__ void __launch_bounds__(256, 2)
proj_qkv(const h16* __restrict__ qb, const h16* __restrict__ kb, const h16* __restrict__ vb,
         const h16* __restrict__ wq, const h16* __restrict__ wk, const h16* __restrict__ wv,
         const int* __restrict__ perm,
         h16* __restrict__ hq, h16* __restrict__ hk, h16* __restrict__ hv)
{
    extern __shared__ __align__(16) char smem[];
    const uint32_t sb = smem_u32(smem);
    const int tid = threadIdx.x, lane = tid & 31, warp = tid >> 5;
    const int wm = warp & 3, wn = warp >> 2;
    const int m0 = blockIdx.y * 128, n0 = blockIdx.x * 128;
    const int z  = blockIdx.z;

    const h16* A = (z == 0) ? qb : (z == 1) ? kb : vb;
    const h16* W = (z == 0) ? wq : (z == 1) ? wk : wv;

    float acc[2][8][4] = {};
    proj_mainloop(A + (size_t)m0 * EMB, W + (size_t)n0 * EMB, sb, tid, lane, wm, wn, acc);

    uint32_t* o = (uint32_t*)((z == 0) ? hq : (z == 1) ? hk : hv);
    const float sc = (z == 0) ? SCALE_Q : 1.0f;
#pragma unroll
    for (int mt = 0; mt < 2; mt++) {
#pragma unroll
        for (int i = 0; i < 2; i++) {
            const int m = m0 + wm * 32 + mt * 16 + (lane >> 2) + i * 8;
            const int b = m >> 11, s = m & (SEQ - 1);
            const int sp = (z == 0) ? s : perm[(b << 11) + s];
#pragma unroll
            for (int nt = 0; nt < 8; nt++) {
                const int n = n0 + wn * 64 + nt * 8 + (lane & 3) * 2;
                const int h = n >> 6, d = n & 63;
                o[(((size_t)(b * HEADS + h) * SEQ + sp) * DKH + d) >> 1] =
                    packh(acc[mt][nt][i*2+0] * sc, acc[mt][nt][i*2+1] * sc);
            }
        }
    }
}

// ---- final projection + residual (fp32 out) ---------------------------------
__global__ void __launch_bounds__(256, 2)
proj_o(const h16* __restrict__ A, const h16* __restrict__ W,
       const float* __restrict__ res, float* __restrict__ out)
{
    extern __shared__ __align__(16) char smem[];
    const uint32_t sb = smem_u32(smem);
    const int tid = threadIdx.x, lane = tid & 31, warp = tid >> 5;
    const int wm = warp & 3, wn = warp >> 2;
    const int m0 = blockIdx.y * 128, n0 = blockIdx.x * 128;

    float acc[2][8][4] = {};
    proj_mainloop(A + (size_t)m0 * EMB, W + (size_t)n0 * EMB, sb, tid, lane, wm, wn, acc);

#pragma unroll
    for (int mt = 0; mt < 2; mt++) {
#pragma unroll
        for (int i = 0; i < 2; i++) {
            const int m = m0 + wm * 32 + mt * 16 + (lane >> 2) + i * 8;
#pragma unroll
            for (int nt = 0; nt < 8; nt++) {
                const int n = n0 + wn * 64 + nt * 8 + (lane & 3) * 2;
                const size_t off = (size_t)m * EMB + n;
                out[off]     = acc[mt][nt][i * 2 + 0] + res[off];
                out[off + 1] = acc[mt][nt][i * 2 + 1] + res[off + 1];
            }
        }
    }
}

// =============================================================================
// fp16 flash attention over COMPACTED keys, 32 query rows per warp.
// CTA = 256 queries x one (b,h); 8 warps x 32 rows; each loaded K/V B-fragment
// feeds BOTH of a warp's M-tiles (halves LDSM per query vs 16-row warps).
// q: [bh][s][64] pre-scaled.  k,v: [bh][s'][64] compacted; tiles past cnt_b
// are skipped, boundary columns >= cnt get p=0.  V via ldmatrix.trans.
// Output fp16 [b*S+s][E].
// =============================================================================
#define ALD      144                   // bytes per 64-fp16 row
#define AQ_BYTES (256*ALD)             // 36864 (Q stage, 256 rows)
#define AK_BYTES (64*ALD)              // 9216
#define ASTAGE   (2*AK_BYTES)          // 18432 (K tile + V tile)
#define ATTN_SMEM (AQ_BYTES + 2*ASTAGE) // 73728

__global__ void __launch_bounds__(256, 1)
attn_h(const h16* __restrict__ q, const h16* __restrict__ k,
       const h16* __restrict__ v, const int* __restrict__ cnt,
       h16* __restrict__ o)
{
    extern __shared__ __align__(16) char smem[];
    const uint32_t sb = smem_u32(smem);
    const int tid = threadIdx.x, lane = tid & 31, warp = tid >> 5;
    const int bh = blockIdx.y, b = bh >> 4, h = bh & 15;
    const int q0 = blockIdx.x * 256;
    const h16* qh = q + (size_t)bh * SEQ * DKH;
    const h16* kh = k + (size_t)bh * SEQ * DKH;
    const h16* vh = v + (size_t)bh * SEQ * DKH;

    const int cntb = cnt[b];
    const int NT = (cntb + 63) >> 6;

    // prologue: stage Q (256 rows, group 0)
#pragma unroll
    for (int i = 0; i < 8; i++) {
        int idx = tid + i * 256;
        int r = idx >> 3, c = idx & 7;
        cp_async16_u(sb + r * ALD + c * 16, qh + (size_t)(q0 + r) * DKH + c * 8);
    }
    cp_commit();

    auto load_stage = [&](int t) {
        const uint32_t base = sb + AQ_BYTES + (t & 1) * ASTAGE;
#pragma unroll
        for (int i = 0; i < 2; i++) {
            int idx = tid + i * 256;
            int r = idx >> 3, c = idx & 7;
            cp_async16_u(base + r * ALD + c * 16,            kh + (size_t)(t * 64 + r) * DKH + c * 8);
            cp_async16_u(base + AK_BYTES + r * ALD + c * 16, vh + (size_t)(t * 64 + r) * DKH + c * 8);
        }
        cp_commit();
    };
    load_stage(0); load_stage(1);

    cp_wait<2>();     // Q done
    __syncthreads();

    // Q fragments: 32 rows per warp = 2 M-tiles x 4 k16-steps
    uint32_t qf[2][4][4];
#pragma unroll
    for (int mt = 0; mt < 2; mt++) {
        const uint32_t qAddr = sb + (uint32_t)((warp * 32 + mt * 16 + (lane & 15)) * ALD
                                               + (lane >> 4) * 16);
#pragma unroll
        for (int ks = 0; ks < 4; ks++)
            ldsm_x4(qf[mt][ks][0], qf[mt][ks][1], qf[mt][ks][2], qf[mt][ks][3],
                    qAddr + ks * 32);
    }

    float Oacc[2][8][4] = {};
    float lsum[2][2] = {};

    const uint32_t bRowOff = (uint32_t)(((lane >> 4) * 8 + (lane & 7)) * ALD
                                        + ((lane >> 3) & 1) * 16);
    const uint32_t vRowOff = (uint32_t)((((lane >> 3) & 1) * 8 + (lane & 7)) * ALD
                                        + (lane >> 4) * 16);

    for (int kt = 0; kt < NT; kt++) {
        if (kt == NT - 1) cp_wait<0>(); else cp_wait<1>();
        __syncthreads();
        const uint32_t SK = sb + AQ_BYTES + (kt & 1) * ASTAGE;
        const uint32_t SV = SK + AK_BYTES;

        // scores for both M-tiles; each K B-fragment loaded once
        float sacc[2][8][4] = {};
#pragma unroll
        for (int ks = 0; ks < 4; ks++) {
            uint32_t bfr[8][2];
#pragma unroll
            for (int nt2 = 0; nt2 < 4; nt2++)
                ldsm_x4(bfr[2*nt2][0], bfr[2*nt2][1], bfr[2*nt2+1][0], bfr[2*nt2+1][1],
                        SK + bRowOff + nt2 * 16 * ALD + ks * 32);
#pragma unroll
            for (int mt = 0; mt < 2; mt++)
#pragma unroll
                for (int nt = 0; nt < 8; nt++)
                    mma_f16(sacc[mt][nt], qf[mt][ks], bfr[nt]);
        }

        // p = exp2(score) (0 past cnt); row-sum partials; pack PV A-fragments
        uint32_t pa[2][4][4];
        const int colbase = (kt << 6) + ((lane & 3) << 1);
#pragma unroll
        for (int mt = 0; mt < 2; mt++) {
#pragma unroll
            for (int nt = 0; nt < 8; nt++) {
                const int c0 = colbase + nt * 8;
                const bool in0 = (c0 < cntb), in1 = (c0 + 1 < cntb);
                const float p0 = in0 ? ex2(sacc[mt][nt][0]) : 0.f;
                const float p1 = in1 ? ex2(sacc[mt][nt][1]) : 0.f;
                const float p2 = in0 ? ex2(sacc[mt][nt][2]) : 0.f;
                const float p3 = in1 ? ex2(sacc[mt][nt][3]) : 0.f;
                lsum[mt][0] += p0 + p1;
                lsum[mt][1] += p2 + p3;
                const int k2 = nt >> 1, odd = (nt & 1) * 2;
                pa[mt][k2][odd + 0] = packh(p0, p1);
                pa[mt][k2][odd + 1] = packh(p2, p3);
            }
        }

        // O += P @ V; each V B-fragment loaded once for both M-tiles
#pragma unroll
        for (int ks2 = 0; ks2 < 4; ks2++) {
            uint32_t bfr[8][2];
#pragma unroll
            for (int nt2 = 0; nt2 < 4; nt2++)
                ldsm_x4t(bfr[2*nt2][0], bfr[2*nt2][1], bfr[2*nt2+1][0], bfr[2*nt2+1][1],
                         SV + vRowOff + ks2 * 16 * ALD + nt2 * 32);
#pragma unroll
            for (int mt = 0; mt < 2; mt++)
#pragma unroll
                for (int nt = 0; nt < 8; nt++)
                    mma_f16(Oacc[mt][nt], pa[mt][ks2], bfr[nt]);
        }

        __syncthreads();
        if (kt + 2 < NT) load_stage(kt + 2);
    }

    // quad-reduce row sums
#pragma unroll
    for (int mt = 0; mt < 2; mt++)
#pragma unroll
        for (int x = 1; x < 4; x <<= 1) {
            lsum[mt][0] += __shfl_xor_sync(0xffffffff, lsum[mt][0], x);
            lsum[mt][1] += __shfl_xor_sync(0xffffffff, lsum[mt][1], x);
        }

    // finalize: /l, pack fp16, write [b*S+s][E]
    uint32_t* ob = (uint32_t*)o;
#pragma unroll
    for (int mt = 0; mt < 2; mt++) {
        const float inv0 = 1.f / lsum[mt][0];
        const float inv1 = 1.f / lsum[mt][1];
        const int s0 = q0 + warp * 32 + mt * 16 + (lane >> 2);
        const size_t r0 = ((size_t)(b * SEQ + s0)) * (EMB / 2) + h * 32;
        const size_t r1 = r0 + 8 * (EMB / 2);
#pragma unroll
        for (int nt = 0; nt < 8; nt++) {
            const int du = nt * 4 + (lane & 3);
            ob[r0 + du] = packh(Oacc[mt][nt][0] * inv0, Oacc[mt][nt][1] * inv0);
            ob[r1 + du] = packh(Oacc[mt][nt][2] * inv1, Oacc[mt][nt][3] * inv1);
        }
    }
}

// =============================================================================
extern "C" void kernel_launch(void* const* d_in, const int* in_sizes, int n_in,
                              void* d_out, int out_size)
{
    const float* Q   = (const float*)d_in[0];
    const float* K   = (const float*)d_in[1];
    const float* V   = (const float*)d_in[2];
    const float* W_Q = (const float*)d_in[3];
    const float* W_K = (const float*)d_in[4];
    const float* W_V = (const float*)d_in[5];
    const float* W_O = (const float*)d_in[6];
    const int*   msk = (const int*)d_in[7];
    float* out = (float*)d_out;

    h16 *qb, *kb, *vb, *wq, *wk, *wv, *wo, *hq, *hk, *hv, *ao;
    int *perm, *cnt;
    cudaGetSymbolAddress((void**)&qb,   g_qb);
    cudaGetSymbolAddress((void**)&kb,   g_kb);
    cudaGetSymbolAddress((void**)&vb,   g_vb);
    cudaGetSymbolAddress((void**)&wq,   g_wq);
    cudaGetSymbolAddress((void**)&wk,   g_wk);
    cudaGetSymbolAddress((void**)&wv,   g_wv);
    cudaGetSymbolAddress((void**)&wo,   g_wo);
    cudaGetSymbolAddress((void**)&hq,   g_q);
    cudaGetSymbolAddress((void**)&hk,   g_k);
    cudaGetSymbolAddress((void**)&hv,   g_v);
    cudaGetSymbolAddress((void**)&ao,   g_ao);
    cudaGetSymbolAddress((void**)&perm, g_perm);
    cudaGetSymbolAddress((void**)&cnt,  g_cnt);

    cudaFuncSetAttribute(proj_qkv, cudaFuncAttributeMaxDynamicSharedMemorySize, PROJ_SMEM);
    cudaFuncSetAttribute(proj_o,   cudaFuncAttributeMaxDynamicSharedMemorySize, PROJ_SMEM);
    cudaFuncSetAttribute(attn_h,   cudaFuncAttributeMaxDynamicSharedMemorySize, ATTN_SMEM);

    cvt_all<<<CVT_BLOCKS, 256>>>(Q, K, V, W_Q, W_K, W_V, W_O,
                                 qb, kb, vb, wq, wk, wv, wo);
    scan_mask<<<BATCH, 256>>>(msk, perm, cnt);

    dim3 gqkv(EMB / 128, MROWS / 128, 3);   // (8, 64, 3)
    proj_qkv<<<gqkv, 256, PROJ_SMEM>>>(qb, kb, vb, wq, wk, wv, perm, hq, hk, hv);

    dim3 ga(SEQ / 256, BATCH * HEADS);      // (8, 64)
    attn_h<<<ga, 256, ATTN_SMEM>>>(hq, hk, hv, cnt, ao);

    dim3 gp(EMB / 128, MROWS / 128);        // (8, 64)
    proj_o<<<gp, 256, PROJ_SMEM>>>(ao, wo, Q, out);
}

// round 15
// speedup vs baseline: 1.0480x; 1.0480x over previous
#include <cuda_runtime.h>
#include <cuda_fp16.h>
#include <cstdint>
#include <cstddef>

// Problem constants
#define BATCH 4
#define SEQ   2048
#define EMB   1024
#define HEADS 16
#define DKH   64
#define MROWS (BATCH*SEQ)      // 8192

#define SCALE_Q 0.18033688f    // 0.125 * log2(e)

typedef __half h16;

// ---------------- scratch (device globals; no allocation allowed) -----------
__device__ h16   g_qb [MROWS*EMB];   // fp16 inputs
__device__ h16   g_kb [MROWS*EMB];
__device__ h16   g_vb [MROWS*EMB];
__device__ h16   g_wq [EMB*EMB];     // fp16 weights
__device__ h16   g_wk [EMB*EMB];
__device__ h16   g_wv [EMB*EMB];
__device__ h16   g_wo [EMB*EMB];
__device__ h16   g_q  [MROWS*EMB];   // q heads [bh][s][64] (pre-scaled by SCALE_Q)
__device__ h16   g_k  [MROWS*EMB];   // k heads [bh][s'][64]  (key-compacted)
__device__ h16   g_v  [MROWS*EMB];   // v heads [bh][s'][64]  (key-compacted)
__device__ h16   g_ao [MROWS*EMB];   // attention output [b*S+s][E]
__device__ int   g_perm[MROWS];      // per-batch compaction permutation
__device__ int   g_cnt [BATCH];      // per-batch unmasked-key counts

// ---------------- helpers ----------------------------------------------------
__device__ __forceinline__ uint32_t smem_u32(const void* p) {
    uint32_t a;
    asm("{ .reg .u64 t; cvta.to.shared.u64 t, %1; cvt.u32.u64 %0, t; }" : "=r"(a) : "l"(p));
    return a;
}
__device__ __forceinline__ void cp_async16_u(uint32_t saddr, const void* gsrc) {
    asm volatile("cp.async.cg.shared.global [%0], [%1], 16;\n" :: "r"(saddr), "l"(gsrc));
}
__device__ __forceinline__ void cp_commit() { asm volatile("cp.async.commit_group;\n"); }
template <int N>
__device__ __forceinline__ void cp_wait() { asm volatile("cp.async.wait_group %0;\n" :: "n"(N)); }

__device__ __forceinline__ void mma_f16(float c[4], const uint32_t a[4], const uint32_t b[2]) {
    asm volatile(
        "mma.sync.aligned.m16n8k16.row.col.f32.f16.f16.f32 "
        "{%0,%1,%2,%3}, {%4,%5,%6,%7}, {%8,%9}, {%0,%1,%2,%3};\n"
        : "+f"(c[0]), "+f"(c[1]), "+f"(c[2]), "+f"(c[3])
        : "r"(a[0]), "r"(a[1]), "r"(a[2]), "r"(a[3]), "r"(b[0]), "r"(b[1]));
}

__device__ __forceinline__ void ldsm_x4(uint32_t& r0, uint32_t& r1, uint32_t& r2, uint32_t& r3,
                                        uint32_t addr) {
    asm volatile("ldmatrix.sync.aligned.m8n8.x4.shared.b16 {%0,%1,%2,%3}, [%4];"
                 : "=r"(r0), "=r"(r1), "=r"(r2), "=r"(r3) : "r"(addr));
}
__device__ __forceinline__ void ldsm_x4t(uint32_t& r0, uint32_t& r1, uint32_t& r2, uint32_t& r3,
                                         uint32_t addr) {
    asm volatile("ldmatrix.sync.aligned.m8n8.x4.trans.shared.b16 {%0,%1,%2,%3}, [%4];"
                 : "=r"(r0), "=r"(r1), "=r"(r2), "=r"(r3) : "r"(addr));
}

__device__ __forceinline__ uint32_t packh(float lo, float hi) {
    __half2 t = __floats2half2_rn(lo, hi);   // .x = lo (low 16 bits)
    return *reinterpret_cast<uint32_t*>(&t);
}

__device__ __forceinline__ float ex2(float x) {
    float y;
    asm("ex2.approx.ftz.f32 %0, %1;" : "=f"(y) : "f"(x));
    return y;
}

// =============================================================================
// fused fp32->fp16 conversion of 3 inputs + 4 weights.
// =============================================================================
#define CVT_NI 1048576
#define CVT_NW 131072
#define CVT_GROUPS (3*CVT_NI + 4*CVT_NW)   // 3670016
#define CVT_BLOCKS (CVT_GROUPS/256)        // 14336

__global__ void cvt_all(const float* __restrict__ Q,  const float* __restrict__ K,
                        const float* __restrict__ V,  const float* __restrict__ WQ,
                        const float* __restrict__ WK, const float* __restrict__ WV,
                        const float* __restrict__ WO,
                        h16* qb, h16* kb, h16* vb, h16* wq, h16* wk, h16* wv, h16* wo)
{
    int i = blockIdx.x * 256 + threadIdx.x;
    const float* src; h16* dst; int off;
    if      (i <     CVT_NI) { src = Q;  dst = qb; off = i; }
    else if (i < 2 * CVT_NI) { src = K;  dst = kb; off = i -     CVT_NI; }
    else if (i < 3 * CVT_NI) { src = V;  dst = vb; off = i - 2 * CVT_NI; }
    else {
        int j = i - 3 * CVT_NI;
        int w = j / CVT_NW;  off = j - w * CVT_NW;
        src = (w == 0) ? WQ : (w == 1) ? WK : (w == 2) ? WV : WO;
        dst = (w == 0) ? wq : (w == 1) ? wk : (w == 2) ? wv : wo;
    }
    const float4* p = (const float4*)src + (size_t)off * 2;
    float4 f0 = p[0], f1 = p[1];
    union { h16 h[8]; uint4 u; } r;
    r.h[0] = __float2half_rn(f0.x); r.h[1] = __float2half_rn(f0.y);
    r.h[2] = __float2half_rn(f0.z); r.h[3] = __float2half_rn(f0.w);
    r.h[4] = __float2half_rn(f1.x); r.h[5] = __float2half_rn(f1.y);
    r.h[6] = __float2half_rn(f1.z); r.h[7] = __float2half_rn(f1.w);
    ((uint4*)dst)[off] = r.u;
}

// =============================================================================
// mask scan: per batch, stable partition of keys (unmasked first).
// =============================================================================
__global__ void scan_mask(const int* __restrict__ msk, int* __restrict__ perm,
                          int* __restrict__ cnt)
{
    __shared__ int wsum[8];
    const int b = blockIdx.x, t = threadIdx.x;
    const int lane = t & 31, w = t >> 5;
    const int* m = msk + b * SEQ;

    int u[8]; int local = 0;
#pragma unroll
    for (int j = 0; j < 8; j++) { u[j] = (m[t * 8 + j] == 0) ? 1 : 0; local += u[j]; }

    int x = local;
#pragma unroll
    for (int d = 1; d < 32; d <<= 1) {
        int y = __shfl_up_sync(0xffffffffu, x, d);
        if (lane >= d) x += y;
    }
    if (lane == 31) wsum[w] = x;
    __syncthreads();
    if (w == 0) {
        int s = (lane < 8) ? wsum[lane] : 0;
#pragma unroll
        for (int d = 1; d < 8; d <<= 1) {
            int y = __shfl_up_sync(0xffffffffu, s, d);
            if (lane >= d) s += y;
        }
        if (lane < 8) wsum[lane] = s;
    }
    __syncthreads();
    const int total = wsum[7];
    int pu = ((w > 0) ? wsum[w - 1] : 0) + (x - local);
#pragma unroll
    for (int j = 0; j < 8; j++) {
        const int s_idx = t * 8 + j;
        perm[b * SEQ + s_idx] = u[j] ? pu : (total + (s_idx - pu));
        pu += u[j];
    }
    if (t == 0) cnt[b] = total;
}

// =============================================================================
// Projection GEMM core: CTA tile 128x128, BK=64, 2-stage cp.async, ldmatrix.
// =============================================================================
#define PLD     144
#define PTILEB  (128*PLD)              // 18432
#define PSTAGEB (2*PTILEB)             // 36864
#define PROJ_SMEM (2*PSTAGEB)          // 73728

__device__ __forceinline__ void proj_mainloop(
    const h16* __restrict__ A, const h16* __restrict__ W,
    uint32_t sb, int tid, int lane, int wm, int wn,
    float acc[2][8][4])
{
    auto load_stage = [&](int kt) {
        const uint32_t base = sb + (kt & 1) * PSTAGEB;
#pragma unroll
        for (int i = 0; i < 4; i++) {
            int idx = tid + i * 256;
            int r = idx >> 3, c = idx & 7;
            cp_async16_u(base + r * PLD + c * 16,          A + (size_t)r * EMB + kt * 64 + c * 8);
            cp_async16_u(base + PTILEB + r * PLD + c * 16, W + (size_t)r * EMB + kt * 64 + c * 8);
        }
        cp_commit();
    };

    const uint32_t aRowOff = (uint32_t)((wm * 32 + (lane & 15)) * PLD + (lane >> 4) * 16);
    const uint32_t bRowOff = (uint32_t)((wn * 64 + (lane >> 4) * 8 + (lane & 7)) * PLD
                                        + ((lane >> 3) & 1) * 16);

    load_stage(0); load_stage(1);
    const int NKT = EMB / 64;
    for (int kt = 0; kt < NKT; kt++) {
        if (kt == NKT - 1) cp_wait<0>(); else cp_wait<1>();
        __syncthreads();
        const uint32_t Sa = sb + (kt & 1) * PSTAGEB;
        const uint32_t Sw = Sa + PTILEB;
#pragma unroll
        for (int ks = 0; ks < 4; ks++) {
            const uint32_t kb = ks * 32;
            uint32_t a[2][4], b[8][2];
            ldsm_x4(a[0][0], a[0][1], a[0][2], a[0][3], Sa + aRowOff + kb);
            ldsm_x4(a[1][0], a[1][1], a[1][2], a[1][3], Sa + aRowOff + 16 * PLD + kb);
#pragma unroll
            for (int nt2 = 0; nt2 < 4; nt2++)
                ldsm_x4(b[2*nt2][0], b[2*nt2][1], b[2*nt2+1][0], b[2*nt2+1][1],
                        Sw + bRowOff + nt2 * 16 * PLD + kb);
#pragma unroll
            for (int mt = 0; mt < 2; mt++)
#pragma unroll
                for (int nt = 0; nt < 8; nt++)
                    mma_f16(acc[mt][nt], a[mt], b[nt]);
        }
        __syncthreads();
        if (kt + 2 < NKT) load_stage(kt + 2);
    }
}

// ---- merged Q/K/V projection: z selects input/weight; K/V rows permuted -----
__global__ void __launch_bounds__(256, 2)
proj_qkv(const h16* __restrict__ qb, const h16* __restrict__ kb, const h16* __restrict__ vb,
         const h16* __restrict__ wq, const h16* __restrict__ wk, const h16* __restrict__ wv,
         const int* __restrict__ perm,
         h16* __restrict__ hq, h16* __restrict__ hk, h16* __restrict__ hv)
{
    extern __shared__ __align__(16) char smem[];
    const uint32_t sb = smem_u32(smem);
    const int tid = threadIdx.x, lane = tid & 31, warp = tid >> 5;
    const int wm = warp & 3, wn = warp >> 2;
    const int m0 = blockIdx.y * 128, n0 = blockIdx.x * 128;
    const int z  = blockIdx.z;

    const h16* A = (z == 0) ? qb : (z == 1) ? kb : vb;
    const h16* W = (z == 0) ? wq : (z == 1) ? wk : wv;

    float acc[2][8][4] = {};
    proj_mainloop(A + (size_t)m0 * EMB, W + (size_t)n0 * EMB, sb, tid, lane, wm, wn, acc);

    uint32_t* o = (uint32_t*)((z == 0) ? hq : (z == 1) ? hk : hv);
    const float sc = (z == 0) ? SCALE_Q : 1.0f;
#pragma unroll
    for (int mt = 0; mt < 2; mt++) {
#pragma unroll
        for (int i = 0; i < 2; i++) {
            const int m = m0 + wm * 32 + mt * 16 + (lane >> 2) + i * 8;
            const int b = m >> 11, s = m & (SEQ - 1);
            const int sp = (z == 0) ? s : perm[(b << 11) + s];
#pragma unroll
            for (int nt = 0; nt < 8; nt++) {
                const int n = n0 + wn * 64 + nt * 8 + (lane & 3) * 2;
                const int h = n >> 6, d = n & 63;
                o[(((size_t)(b * HEADS + h) * SEQ + sp) * DKH + d) >> 1] =
                    packh(acc[mt][nt][i*2+0] * sc, acc[mt][nt][i*2+1] * sc);
            }
        }
    }
}

// ---- final projection + residual (fp32 out) ---------------------------------
__global__ void __launch_bounds__(256, 2)
proj_o(const h16* __restrict__ A, const h16* __restrict__ W,
       const float* __restrict__ res, float* __restrict__ out)
{
    extern __shared__ __align__(16) char smem[];
    const uint32_t sb = smem_u32(smem);
    const int tid = threadIdx.x, lane = tid & 31, warp = tid >> 5;
    const int wm = warp & 3, wn = warp >> 2;
    const int m0 = blockIdx.y * 128, n0 = blockIdx.x * 128;

    float acc[2][8][4] = {};
    proj_mainloop(A + (size_t)m0 * EMB, W + (size_t)n0 * EMB, sb, tid, lane, wm, wn, acc);

#pragma unroll
    for (int mt = 0; mt < 2; mt++) {
#pragma unroll
        for (int i = 0; i < 2; i++) {
            const int m = m0 + wm * 32 + mt * 16 + (lane >> 2) + i * 8;
#pragma unroll
            for (int nt = 0; nt < 8; nt++) {
                const int n = n0 + wn * 64 + nt * 8 + (lane & 3) * 2;
                const size_t off = (size_t)m * EMB + n;
                out[off]     = acc[mt][nt][i * 2 + 0] + res[off];
                out[off + 1] = acc[mt][nt][i * 2 + 1] + res[off + 1];
            }
        }
    }
}

// =============================================================================
// fp16 flash attention over COMPACTED keys.
// CTA = 128 queries x one (b,h); 4 warps (128 threads) x 32 rows/warp.
// Each loaded K/V B-fragment feeds BOTH of a warp's M-tiles (R12's sharing),
// while the small CTA keeps 2 CTAs/SM resident (R11's latency hiding).
// q: [bh][s][64] pre-scaled.  k,v: [bh][s'][64] compacted; tiles past cnt_b
// skipped, boundary columns >= cnt get p=0.  V via ldmatrix.trans.
// Output fp16 [b*S+s][E].
// =============================================================================
#define ALD      144                   // bytes per 64-fp16 row
#define AQ_BYTES (128*ALD)             // 18432 (Q stage, 128 rows)
#define AK_BYTES (64*ALD)              // 9216
#define ASTAGE   (2*AK_BYTES)          // 18432 (K tile + V tile)
#define ATTN_SMEM (AQ_BYTES + 2*ASTAGE) // 55296

__global__ void __launch_bounds__(128, 2)
attn_h(const h16* __restrict__ q, const h16* __restrict__ k,
       const h16* __restrict__ v, const int* __restrict__ cnt,
       h16* __restrict__ o)
{
    extern __shared__ __align__(16) char smem[];
    const uint32_t sb = smem_u32(smem);
    const int tid = threadIdx.x, lane = tid & 31, warp = tid >> 5;   // 4 warps
    const int bh = blockIdx.y, b = bh >> 4, h = bh & 15;
    const int q0 = blockIdx.x * 128;
    const h16* qh = q + (size_t)bh * SEQ * DKH;
    const h16* kh = k + (size_t)bh * SEQ * DKH;
    const h16* vh = v + (size_t)bh * SEQ * DKH;

    const int cntb = cnt[b];
    const int NT = (cntb + 63) >> 6;

    // prologue: stage Q (128 rows = 1024 chunks, 128 threads -> 8 each)
#pragma unroll
    for (int i = 0; i < 8; i++) {
        int idx = tid + i * 128;
        int r = idx >> 3, c = idx & 7;
        cp_async16_u(sb + r * ALD + c * 16, qh + (size_t)(q0 + r) * DKH + c * 8);
    }
    cp_commit();

    auto load_stage = [&](int t) {
        const uint32_t base = sb + AQ_BYTES + (t & 1) * ASTAGE;
#pragma unroll
        for (int i = 0; i < 4; i++) {          // K: 512 chunks / 128 thr
            int idx = tid + i * 128;
            int r = idx >> 3, c = idx & 7;
            cp_async16_u(base + r * ALD + c * 16,            kh + (size_t)(t * 64 + r) * DKH + c * 8);
            cp_async16_u(base + AK_BYTES + r * ALD + c * 16, vh + (size_t)(t * 64 + r) * DKH + c * 8);
        }
        cp_commit();
    };
    load_stage(0); load_stage(1);

    cp_wait<2>();     // Q done
    __syncthreads();

    // Q fragments: 32 rows per warp = 2 M-tiles x 4 k16-steps
    uint32_t qf[2][4][4];
#pragma unroll
    for (int mt = 0; mt < 2; mt++) {
        const uint32_t qAddr = sb + (uint32_t)((warp * 32 + mt * 16 + (lane & 15)) * ALD
                                               + (lane >> 4) * 16);
#pragma unroll
        for (int ks = 0; ks < 4; ks++)
            ldsm_x4(qf[mt][ks][0], qf[mt][ks][1], qf[mt][ks][2], qf[mt][ks][3],
                    qAddr + ks * 32);
    }

    float Oacc[2][8][4] = {};
    float lsum[2][2] = {};

    const uint32_t bRowOff = (uint32_t)(((lane >> 4) * 8 + (lane & 7)) * ALD
                                        + ((lane >> 3) & 1) * 16);
    const uint32_t vRowOff = (uint32_t)((((lane >> 3) & 1) * 8 + (lane & 7)) * ALD
                                        + (lane >> 4) * 16);

    for (int kt = 0; kt < NT; kt++) {
        if (kt == NT - 1) cp_wait<0>(); else cp_wait<1>();
        __syncthreads();
        const uint32_t SK = sb + AQ_BYTES + (kt & 1) * ASTAGE;
        const uint32_t SV = SK + AK_BYTES;

        // scores for both M-tiles; each K B-fragment loaded once
        float sacc[2][8][4] = {};
#pragma unroll
        for (int ks = 0; ks < 4; ks++) {
            uint32_t bfr[8][2];
#pragma unroll
            for (int nt2 = 0; nt2 < 4; nt2++)
                ldsm_x4(bfr[2*nt2][0], bfr[2*nt2][1], bfr[2*nt2+1][0], bfr[2*nt2+1][1],
                        SK + bRowOff + nt2 * 16 * ALD + ks * 32);
#pragma unroll
            for (int mt = 0; mt < 2; mt++)
#pragma unroll
                for (int nt = 0; nt < 8; nt++)
                    mma_f16(sacc[mt][nt], qf[mt][ks], bfr[nt]);
        }

        // p = exp2(score) (0 past cnt); row-sum partials; pack PV A-fragments
        uint32_t pa[2][4][4];
        const int colbase = (kt << 6) + ((lane & 3) << 1);
#pragma unroll
        for (int mt = 0; mt < 2; mt++) {
#pragma unroll
            for (int nt = 0; nt < 8; nt++) {
                const int c0 = colbase + nt * 8;
                const bool in0 = (c0 < cntb), in1 = (c0 + 1 < cntb);
                const float p0 = in0 ? ex2(sacc[mt][nt][0]) : 0.f;
                const float p1 = in1 ? ex2(sacc[mt][nt][1]) : 0.f;
                const float p2 = in0 ? ex2(sacc[mt][nt][2]) : 0.f;
                const float p3 = in1 ? ex2(sacc[mt][nt][3]) : 0.f;
                lsum[mt][0] += p0 + p1;
                lsum[mt][1] += p2 + p3;
                const int k2 = nt >> 1, odd = (nt & 1) * 2;
                pa[mt][k2][odd + 0] = packh(p0, p1);
                pa[mt][k2][odd + 1] = packh(p2, p3);
            }
        }

        // O += P @ V; each V B-fragment loaded once for both M-tiles
#pragma unroll
        for (int ks2 = 0; ks2 < 4; ks2++) {
            uint32_t bfr[8][2];
#pragma unroll
            for (int nt2 = 0; nt2 < 4; nt2++)
                ldsm_x4t(bfr[2*nt2][0], bfr[2*nt2][1], bfr[2*nt2+1][0], bfr[2*nt2+1][1],
                         SV + vRowOff + ks2 * 16 * ALD + nt2 * 32);
#pragma unroll
            for (int mt = 0; mt < 2; mt++)
#pragma unroll
                for (int nt = 0; nt < 8; nt++)
                    mma_f16(Oacc[mt][nt], pa[mt][ks2], bfr[nt]);
        }

        __syncthreads();
        if (kt + 2 < NT) load_stage(kt + 2);
    }

    // quad-reduce row sums
#pragma unroll
    for (int mt = 0; mt < 2; mt++)
#pragma unroll
        for (int x = 1; x < 4; x <<= 1) {
            lsum[mt][0] += __shfl_xor_sync(0xffffffff, lsum[mt][0], x);
            lsum[mt][1] += __shfl_xor_sync(0xffffffff, lsum[mt][1], x);
        }

    // finalize: /l, pack fp16, write [b*S+s][E]
    uint32_t* ob = (uint32_t*)o;
#pragma unroll
    for (int mt = 0; mt < 2; mt++) {
        const float inv0 = 1.f / lsum[mt][0];
        const float inv1 = 1.f / lsum[mt][1];
        const int s0 = q0 + warp * 32 + mt * 16 + (lane >> 2);
        const size_t r0 = ((size_t)(b * SEQ + s0)) * (EMB / 2) + h * 32;
        const size_t r1 = r0 + 8 * (EMB / 2);
#pragma unroll
        for (int nt = 0; nt < 8; nt++) {
            const int du = nt * 4 + (lane & 3);
            ob[r0 + du] = packh(Oacc[mt][nt][0] * inv0, Oacc[mt][nt][1] * inv0);
            ob[r1 + du] = packh(Oacc[mt][nt][2] * inv1, Oacc[mt][nt][3] * inv1);
        }
    }
}

// =============================================================================
extern "C" void kernel_launch(void* const* d_in, const int* in_sizes, int n_in,
                              void* d_out, int out_size)
{
    const float* Q   = (const float*)d_in[0];
    const float* K   = (const float*)d_in[1];
    const float* V   = (const float*)d_in[2];
    const float* W_Q = (const float*)d_in[3];
    const float* W_K = (const float*)d_in[4];
    const float* W_V = (const float*)d_in[5];
    const float* W_O = (const float*)d_in[6];
    const int*   msk = (const int*)d_in[7];
    float* out = (float*)d_out;

    h16 *qb, *kb, *vb, *wq, *wk, *wv, *wo, *hq, *hk, *hv, *ao;
    int *perm, *cnt;
    cudaGetSymbolAddress((void**)&qb,   g_qb);
    cudaGetSymbolAddress((void**)&kb,   g_kb);
    cudaGetSymbolAddress((void**)&vb,   g_vb);
    cudaGetSymbolAddress((void**)&wq,   g_wq);
    cudaGetSymbolAddress((void**)&wk,   g_wk);
    cudaGetSymbolAddress((void**)&wv,   g_wv);
    cudaGetSymbolAddress((void**)&wo,   g_wo);
    cudaGetSymbolAddress((void**)&hq,   g_q);
    cudaGetSymbolAddress((void**)&hk,   g_k);
    cudaGetSymbolAddress((void**)&hv,   g_v);
    cudaGetSymbolAddress((void**)&ao,   g_ao);
    cudaGetSymbolAddress((void**)&perm, g_perm);
    cudaGetSymbolAddress((void**)&cnt,  g_cnt);

    cudaFuncSetAttribute(proj_qkv, cudaFuncAttributeMaxDynamicSharedMemorySize, PROJ_SMEM);
    cudaFuncSetAttribute(proj_o,   cudaFuncAttributeMaxDynamicSharedMemorySize, PROJ_SMEM);
    cudaFuncSetAttribute(attn_h,   cudaFuncAttributeMaxDynamicSharedMemorySize, ATTN_SMEM);

    cvt_all<<<CVT_BLOCKS, 256>>>(Q, K, V, W_Q, W_K, W_V, W_O,
                                 qb, kb, vb, wq, wk, wv, wo);
    scan_mask<<<BATCH, 256>>>(msk, perm, cnt);

    dim3 gqkv(EMB / 128, MROWS / 128, 3);   // (8, 64, 3)
    proj_qkv<<<gqkv, 256, PROJ_SMEM>>>(qb, kb, vb, wq, wk, wv, perm, hq, hk, hv);

    dim3 ga(SEQ / 128, BATCH * HEADS);      // (16, 64)
    attn_h<<<ga, 128, ATTN_SMEM>>>(hq, hk, hv, cnt, ao);

    dim3 gp(EMB / 128, MROWS / 128);        // (8, 64)
    proj_o<<<gp, 256, PROJ_SMEM>>>(ao, wo, Q, out);
}